// round 2
// baseline (speedup 1.0000x reference)
#include <cuda_runtime.h>
#include <cstdint>

// ============================================================================
// SelfAttention: out = softmax( (xWq^T+bq)(xWk^T+bk)^T ) (xWv^T+bv)
// B=4, S=2048, H=1024  (fp32 in/out)
// Precision strategy: 3xTF32 (hi/lo split) for QKV + scores, 1xTF32 for PV.
// ============================================================================

#define BATCH 4
#define SEQ   2048
#define HID   1024
#define MTOT  (BATCH*SEQ)          // 8192

#define BM 128
#define BN 128
#define THREADS 256
#define BSTRIDE2 132               // BN + 4 pad (words), for [K][N] B tiles

// Scratch (device globals: allocation-free per harness rules)
__device__ float g_q[(size_t)MTOT * HID];          // 32 MB
__device__ float g_k[(size_t)MTOT * HID];          // 32 MB
__device__ float g_v[(size_t)MTOT * HID];          // 32 MB
__device__ float g_s[(size_t)BATCH * SEQ * SEQ];   // 64 MB

// ----------------------------------------------------------------------------
// helpers
// ----------------------------------------------------------------------------
__device__ __forceinline__ uint32_t f2tf(float x) {
    uint32_t u;
    asm("cvt.rna.tf32.f32 %0, %1;" : "=r"(u) : "f"(x));
    return u;
}

__device__ __forceinline__ void mma_tf32(float c[4],
                                         const uint32_t a[4],
                                         const uint32_t b[2]) {
    asm volatile(
        "mma.sync.aligned.m16n8k8.row.col.f32.tf32.tf32.f32 "
        "{%0,%1,%2,%3}, {%4,%5,%6,%7}, {%8,%9}, {%0,%1,%2,%3};\n"
        : "+f"(c[0]), "+f"(c[1]), "+f"(c[2]), "+f"(c[3])
        : "r"(a[0]), "r"(a[1]), "r"(a[2]), "r"(a[3]), "r"(b[0]), "r"(b[1]));
}

// split x into hi (tf32) + lo (tf32 of residual); x - hi is exact in fp32
__device__ __forceinline__ void tf_split(float x, uint32_t& hi, uint32_t& lo) {
    hi = f2tf(x);
    lo = f2tf(x - __uint_as_float(hi));
}

// ----------------------------------------------------------------------------
// Generic 128x128 tile GEMM core.
//   BKMAJOR=true : B is [N,K] row-major -> C = A * B^T
//   BKMAJOR=false: B is [K,N] row-major -> C = A * B
//   SPLIT=true   : 3xTF32 compensated (BK=16), else plain tf32 (BK=32)
// All dims are multiples of the tile sizes here; no bounds checks.
// ----------------------------------------------------------------------------
template<bool BKMAJOR, bool HAS_BIAS, bool SPLIT>
__device__ __forceinline__ void gemm_core(
    const float* __restrict__ A, int lda,
    const float* __restrict__ B, int ldb,
    float* __restrict__ C, int ldc,
    const float* __restrict__ bias,
    int K)
{
    constexpr int BKv   = SPLIT ? 16 : 32;
    constexpr int AST   = BKv + 4;
    constexpr int ATILE = BM * AST;                       // words per component
    constexpr int BTILE = BKMAJOR ? (BN * AST) : (BKv * BSTRIDE2);

    __shared__ uint32_t As[(SPLIT ? 2 : 1) * ATILE];      // [hi | lo]
    __shared__ uint32_t Bs[(SPLIT ? 2 : 1) * BTILE];

    const int tid  = threadIdx.x;
    const int lane = tid & 31;
    const int warp = tid >> 5;
    const int wm   = warp & 3;        // 0..3  -> 32-row warp tile
    const int wn   = warp >> 2;       // 0..1  -> 64-col warp tile
    const int gid  = lane >> 2;       // 0..7
    const int qid  = lane & 3;        // 0..3

    const int tm0 = blockIdx.y * BM;
    const int tn0 = blockIdx.x * BN;

    float acc[2][8][4];
    #pragma unroll
    for (int mi = 0; mi < 2; ++mi)
        #pragma unroll
        for (int ni = 0; ni < 8; ++ni)
            #pragma unroll
            for (int j = 0; j < 4; ++j) acc[mi][ni][j] = 0.f;

    // elements per tile row in float4 units
    constexpr int A_F4_PER_ROW = BKv / 4;                 // 4 or 8
    constexpr int A_F4_TOTAL   = BM * A_F4_PER_ROW;       // 512 or 1024
    constexpr int A_ITERS      = A_F4_TOTAL / THREADS;    // 2 or 4

    for (int k0 = 0; k0 < K; k0 += BKv) {
        // ---- load A tile [BM][BKv] ----
        #pragma unroll
        for (int i = 0; i < A_ITERS; ++i) {
            int slot = tid + i * THREADS;
            int r  = slot / A_F4_PER_ROW;
            int c4 = slot % A_F4_PER_ROW;
            const float4 v = *reinterpret_cast<const float4*>(
                A + (size_t)(tm0 + r) * lda + k0 + c4 * 4);
            uint32_t* dh = &As[r * AST + c4 * 4];
            if (SPLIT) {
                uint32_t* dl = dh + ATILE;
                tf_split(v.x, dh[0], dl[0]); tf_split(v.y, dh[1], dl[1]);
                tf_split(v.z, dh[2], dl[2]); tf_split(v.w, dh[3], dl[3]);
            } else {
                dh[0] = f2tf(v.x); dh[1] = f2tf(v.y);
                dh[2] = f2tf(v.z); dh[3] = f2tf(v.w);
            }
        }
        // ---- load B tile ----
        if (BKMAJOR) {
            #pragma unroll
            for (int i = 0; i < A_ITERS; ++i) {
                int slot = tid + i * THREADS;
                int r  = slot / A_F4_PER_ROW;
                int c4 = slot % A_F4_PER_ROW;
                const float4 v = *reinterpret_cast<const float4*>(
                    B + (size_t)(tn0 + r) * ldb + k0 + c4 * 4);
                uint32_t* dh = &Bs[r * AST + c4 * 4];
                if (SPLIT) {
                    uint32_t* dl = dh + BTILE;
                    tf_split(v.x, dh[0], dl[0]); tf_split(v.y, dh[1], dl[1]);
                    tf_split(v.z, dh[2], dl[2]); tf_split(v.w, dh[3], dl[3]);
                } else {
                    dh[0] = f2tf(v.x); dh[1] = f2tf(v.y);
                    dh[2] = f2tf(v.z); dh[3] = f2tf(v.w);
                }
            }
        } else {
            // B[K,N]: tile [BKv][BN]; BN/4=32 float4 per row
            constexpr int B_ITERS = (BKv * 32) / THREADS; // 2 or 4
            #pragma unroll
            for (int i = 0; i < B_ITERS; ++i) {
                int slot = tid + i * THREADS;
                int r  = slot >> 5;
                int c4 = slot & 31;
                const float4 v = *reinterpret_cast<const float4*>(
                    B + (size_t)(k0 + r) * ldb + tn0 + c4 * 4);
                uint32_t* dh = &Bs[r * BSTRIDE2 + c4 * 4];
                if (SPLIT) {
                    uint32_t* dl = dh + BTILE;
                    tf_split(v.x, dh[0], dl[0]); tf_split(v.y, dh[1], dl[1]);
                    tf_split(v.z, dh[2], dl[2]); tf_split(v.w, dh[3], dl[3]);
                } else {
                    dh[0] = f2tf(v.x); dh[1] = f2tf(v.y);
                    dh[2] = f2tf(v.z); dh[3] = f2tf(v.w);
                }
            }
        }
        __syncthreads();

        // ---- compute ----
        #pragma unroll
        for (int kk = 0; kk < BKv / 8; ++kk) {
            const int k8 = kk * 8;
            uint32_t ah[2][4], al[2][4];
            #pragma unroll
            for (int mi = 0; mi < 2; ++mi) {
                int r0 = wm * 32 + mi * 16 + gid;
                ah[mi][0] = As[(r0    ) * AST + k8 + qid];
                ah[mi][1] = As[(r0 + 8) * AST + k8 + qid];
                ah[mi][2] = As[(r0    ) * AST + k8 + qid + 4];
                ah[mi][3] = As[(r0 + 8) * AST + k8 + qid + 4];
                if (SPLIT) {
                    al[mi][0] = As[ATILE + (r0    ) * AST + k8 + qid];
                    al[mi][1] = As[ATILE + (r0 + 8) * AST + k8 + qid];
                    al[mi][2] = As[ATILE + (r0    ) * AST + k8 + qid + 4];
                    al[mi][3] = As[ATILE + (r0 + 8) * AST + k8 + qid + 4];
                }
            }
            uint32_t bh[8][2], bl[8][2];
            #pragma unroll
            for (int ni = 0; ni < 8; ++ni) {
                if (BKMAJOR) {
                    int nr = wn * 64 + ni * 8 + gid;
                    bh[ni][0] = Bs[nr * AST + k8 + qid];
                    bh[ni][1] = Bs[nr * AST + k8 + qid + 4];
                    if (SPLIT) {
                        bl[ni][0] = Bs[BTILE + nr * AST + k8 + qid];
                        bl[ni][1] = Bs[BTILE + nr * AST + k8 + qid + 4];
                    }
                } else {
                    int nc = wn * 64 + ni * 8 + gid;
                    bh[ni][0] = Bs[(k8 + qid    ) * BSTRIDE2 + nc];
                    bh[ni][1] = Bs[(k8 + qid + 4) * BSTRIDE2 + nc];
                    if (SPLIT) {
                        bl[ni][0] = Bs[BTILE + (k8 + qid    ) * BSTRIDE2 + nc];
                        bl[ni][1] = Bs[BTILE + (k8 + qid + 4) * BSTRIDE2 + nc];
                    }
                }
            }
            #pragma unroll
            for (int mi = 0; mi < 2; ++mi)
                #pragma unroll
                for (int ni = 0; ni < 8; ++ni) {
                    mma_tf32(acc[mi][ni], ah[mi], bh[ni]);
                    if (SPLIT) {
                        mma_tf32(acc[mi][ni], ah[mi], bl[ni]);
                        mma_tf32(acc[mi][ni], al[mi], bh[ni]);
                    }
                }
        }
        __syncthreads();
    }

    // ---- epilogue ----
    #pragma unroll
    for (int mi = 0; mi < 2; ++mi) {
        #pragma unroll
        for (int ni = 0; ni < 8; ++ni) {
            int r = tm0 + wm * 32 + mi * 16 + gid;
            int c = tn0 + wn * 64 + ni * 8 + qid * 2;
            float bb0 = 0.f, bb1 = 0.f;
            if (HAS_BIAS) { bb0 = bias[c]; bb1 = bias[c + 1]; }
            C[(size_t)r * ldc + c    ]       = acc[mi][ni][0] + bb0;
            C[(size_t)r * ldc + c + 1]       = acc[mi][ni][1] + bb1;
            C[(size_t)(r + 8) * ldc + c    ] = acc[mi][ni][2] + bb0;
            C[(size_t)(r + 8) * ldc + c + 1] = acc[mi][ni][3] + bb1;
        }
    }
}

// ----------------------------------------------------------------------------
// kernels
// ----------------------------------------------------------------------------
__global__ __launch_bounds__(THREADS)
void qkv_kernel(const float* __restrict__ x,
                const float* __restrict__ Wq, const float* __restrict__ bq,
                const float* __restrict__ Wk, const float* __restrict__ bk,
                const float* __restrict__ Wv, const float* __restrict__ bv)
{
    const float* W; const float* b; float* out;
    if (blockIdx.z == 0)      { W = Wq; b = bq; out = g_q; }
    else if (blockIdx.z == 1) { W = Wk; b = bk; out = g_k; }
    else                      { W = Wv; b = bv; out = g_v; }
    gemm_core<true, true, true>(x, HID, W, HID, out, HID, b, HID);
}

__global__ __launch_bounds__(THREADS)
void scores_kernel()
{
    const size_t bo = (size_t)blockIdx.z * SEQ * HID;
    gemm_core<true, false, true>(g_q + bo, HID, g_k + bo, HID,
                                 g_s + (size_t)blockIdx.z * SEQ * SEQ, SEQ,
                                 nullptr, HID);
}

__global__ __launch_bounds__(256)
void softmax_kernel()
{
    float* p = g_s + (size_t)blockIdx.x * SEQ;
    const int t = threadIdx.x;
    __shared__ float red[8];

    float4* p4 = reinterpret_cast<float4*>(p);
    float4 u0 = p4[t];
    float4 u1 = p4[t + 256];

    float m = fmaxf(fmaxf(fmaxf(u0.x, u0.y), fmaxf(u0.z, u0.w)),
                    fmaxf(fmaxf(u1.x, u1.y), fmaxf(u1.z, u1.w)));
    #pragma unroll
    for (int off = 16; off; off >>= 1)
        m = fmaxf(m, __shfl_xor_sync(0xffffffffu, m, off));
    if ((t & 31) == 0) red[t >> 5] = m;
    __syncthreads();
    if (t < 8) {
        float mm = red[t];
        #pragma unroll
        for (int off = 4; off; off >>= 1)
            mm = fmaxf(mm, __shfl_xor_sync(0xffu, mm, off));
        if (t == 0) red[0] = mm;
    }
    __syncthreads();
    m = red[0];
    __syncthreads();

    u0.x = expf(u0.x - m); u0.y = expf(u0.y - m);
    u0.z = expf(u0.z - m); u0.w = expf(u0.w - m);
    u1.x = expf(u1.x - m); u1.y = expf(u1.y - m);
    u1.z = expf(u1.z - m); u1.w = expf(u1.w - m);

    float s = (u0.x + u0.y + u0.z + u0.w) + (u1.x + u1.y + u1.z + u1.w);
    #pragma unroll
    for (int off = 16; off; off >>= 1)
        s += __shfl_xor_sync(0xffffffffu, s, off);
    if ((t & 31) == 0) red[t >> 5] = s;
    __syncthreads();
    if (t < 8) {
        float ss = red[t];
        #pragma unroll
        for (int off = 4; off; off >>= 1)
            ss += __shfl_xor_sync(0xffu, ss, off);
        if (t == 0) red[0] = ss;
    }
    __syncthreads();
    const float inv = 1.0f / red[0];

    u0.x *= inv; u0.y *= inv; u0.z *= inv; u0.w *= inv;
    u1.x *= inv; u1.y *= inv; u1.z *= inv; u1.w *= inv;
    p4[t] = u0;
    p4[t + 256] = u1;
}

__global__ __launch_bounds__(THREADS)
void pv_kernel(float* __restrict__ out)
{
    const size_t so = (size_t)blockIdx.z * SEQ * SEQ;
    const size_t vo = (size_t)blockIdx.z * SEQ * HID;
    gemm_core<false, false, false>(g_s + so, SEQ, g_v + vo, HID,
                                   out + vo, HID, nullptr, SEQ);
}

// ----------------------------------------------------------------------------
// launch
// ----------------------------------------------------------------------------
extern "C" void kernel_launch(void* const* d_in, const int* in_sizes, int n_in,
                              void* d_out, int out_size)
{
    (void)in_sizes; (void)n_in; (void)out_size;
    const float* x  = (const float*)d_in[0];
    const float* Wq = (const float*)d_in[1];
    const float* bq = (const float*)d_in[2];
    const float* Wk = (const float*)d_in[3];
    const float* bk = (const float*)d_in[4];
    const float* Wv = (const float*)d_in[5];
    const float* bv = (const float*)d_in[6];
    float* out = (float*)d_out;

    // 1) q/k/v = x W^T + b        (M=8192, N=1024, K=1024) x3, 3xTF32
    qkv_kernel<<<dim3(HID / BN, MTOT / BM, 3), THREADS>>>(x, Wq, bq, Wk, bk, Wv, bv);
    // 2) scores = q k^T           (per batch: M=N=2048, K=1024), 3xTF32
    scores_kernel<<<dim3(SEQ / BN, SEQ / BM, BATCH), THREADS>>>();
    // 3) softmax rows (8192 rows of 2048)
    softmax_kernel<<<BATCH * SEQ, 256>>>();
    // 4) out = P v                (per batch: M=2048, N=1024, K=2048), 1xTF32
    pv_kernel<<<dim3(HID / BN, SEQ / BM, BATCH), THREADS>>>(out);
}

// round 4
// speedup vs baseline: 2.7147x; 2.7147x over previous
#include <cuda_runtime.h>
#include <cuda_fp16.h>
#include <cstdint>

// ============================================================================
// SelfAttention: out = softmax( (xWq^T+bq)(xWk^T+bk)^T ) (xWv^T+bv)
// B=4, S=2048, H=1024 (fp32 in/out)
// All GEMMs: legacy mma.sync m16n8k16 fp16 (tcgen05 unavailable: target sm_100)
// Precision: 3x-FP16 hi/lo split (== 3xTF32: same 11-bit mantissa) for QKV and
// scores; 1x-FP16 for PV.  cp.async 3-stage pipeline + ldmatrix fragments.
// ============================================================================

#define BATCH 4
#define SEQ   2048
#define HID   1024
#define MTOT  (BATCH*SEQ)          // 8192

// ---- scratch (device globals; allocation-free per harness rules) ----
__device__ __half g_xh[(size_t)MTOT * HID];
__device__ __half g_xl[(size_t)MTOT * HID];
__device__ __half g_wh[(size_t)3 * HID * HID];
__device__ __half g_wl[(size_t)3 * HID * HID];
__device__ __half g_qh[(size_t)MTOT * HID];
__device__ __half g_ql[(size_t)MTOT * HID];
__device__ __half g_kh[(size_t)MTOT * HID];
__device__ __half g_kl[(size_t)MTOT * HID];
__device__ __half g_vh[(size_t)MTOT * HID];
__device__ float  g_s [(size_t)BATCH * SEQ * SEQ];
__device__ __half g_p [(size_t)BATCH * SEQ * SEQ];

// ----------------------------------------------------------------------------
// helpers
// ----------------------------------------------------------------------------
__device__ __forceinline__ uint32_t smem_u32(const void* p) {
    uint32_t a;
    asm("{ .reg .u64 t; cvta.to.shared.u64 t, %1; cvt.u32.u64 %0, t; }"
        : "=r"(a) : "l"(p));
    return a;
}

__device__ __forceinline__ void cpa16(uint32_t dst, const void* src) {
    asm volatile("cp.async.cg.shared.global [%0], [%1], 16;"
                 :: "r"(dst), "l"(src));
}

__device__ __forceinline__ void ldsm4(uint32_t& r0, uint32_t& r1,
                                      uint32_t& r2, uint32_t& r3, uint32_t a) {
    asm volatile("ldmatrix.sync.aligned.m8n8.x4.shared.b16 {%0,%1,%2,%3}, [%4];"
                 : "=r"(r0), "=r"(r1), "=r"(r2), "=r"(r3) : "r"(a));
}
__device__ __forceinline__ void ldsm4t(uint32_t& r0, uint32_t& r1,
                                       uint32_t& r2, uint32_t& r3, uint32_t a) {
    asm volatile("ldmatrix.sync.aligned.m8n8.x4.trans.shared.b16 {%0,%1,%2,%3}, [%4];"
                 : "=r"(r0), "=r"(r1), "=r"(r2), "=r"(r3) : "r"(a));
}

__device__ __forceinline__ void mma16816(float c[4], const uint32_t a[4],
                                         uint32_t b0, uint32_t b1) {
    asm volatile(
        "mma.sync.aligned.m16n8k16.row.col.f32.f16.f16.f32 "
        "{%0,%1,%2,%3}, {%4,%5,%6,%7}, {%8,%9}, {%0,%1,%2,%3};\n"
        : "+f"(c[0]), "+f"(c[1]), "+f"(c[2]), "+f"(c[3])
        : "r"(a[0]), "r"(a[1]), "r"(a[2]), "r"(a[3]), "r"(b0), "r"(b1));
}

// ============================================================================
// GEMM core: 128x128 CTA tile, BK=64 halves, 3-stage cp.async pipeline.
//   BNN=false: TN — A[M,K], B[N,K] both K-major (C = A * B^T)
//   BNN=true : NN — A[M,K] K-major, B[K,N] N-major (C = A * B)
//   NSPLIT=3 : products Ah*Bh + Ah*Bl + Al*Bh ; NSPLIT=1 : Ah*Bh
//   EPI: 0 = fp32 store; 1 = bias + hi/lo half split store; 2 = bias + half
// Dims are exact multiples of all tiles.  smem/stage: A 16KB + B 16KB.
// ============================================================================
template<int KVAL, int NSPLIT, bool BNN, int EPI>
__device__ __forceinline__ void gemm_main(
    const __half* __restrict__ Ah, const __half* __restrict__ Al,
    const __half* __restrict__ Bh, const __half* __restrict__ Bl,
    int lda, int ldb,
    float* __restrict__ Cf, __half* __restrict__ Ch, __half* __restrict__ Cl,
    const float* __restrict__ bias, int ldc)
{
    constexpr int NC = KVAL / 64;
    constexpr int T  = NSPLIT * NC;
    constexpr int STAGES = 3;
    constexpr uint32_t STAGE = 32768u;

    extern __shared__ __align__(16) char smem[];
    const uint32_t sbase = smem_u32(smem);

    const int tid  = threadIdx.x;
    const int lane = tid & 31;
    const int warp = tid >> 5;
    const int wm = warp & 3;          // 32-row warp tile
    const int wn = warp >> 2;         // 64-col warp tile
    const int tm0 = blockIdx.y * 128;
    const int tn0 = blockIdx.x * 128;

    // ---- cp.async slot precompute (4 x 16B per thread per tile) ----
    uint32_t dA[4], gA[4], dB[4], gB[4];
    #pragma unroll
    for (int i = 0; i < 4; ++i) {
        const int slot = tid + i * 256;
        { const int r = slot >> 3, c = slot & 7;
          dA[i] = (uint32_t)(r * 128 + ((c ^ (r & 7)) << 4));
          gA[i] = (uint32_t)((tm0 + r) * lda + c * 8); }
        if (!BNN) {
            const int r = slot >> 3, c = slot & 7;
            dB[i] = (uint32_t)(r * 128 + ((c ^ (r & 7)) << 4));
            gB[i] = (uint32_t)((tn0 + r) * ldb + c * 8);
        } else {
            const int r = slot >> 4, c = slot & 15;
            dB[i] = (uint32_t)(r * 256 + ((c ^ (r & 7)) << 4));
            gB[i] = (uint32_t)(r * ldb + tn0 + c * 8);
        }
    }

    const __half* const Alist[3] = {Ah, Ah, Al};
    const __half* const Blist[3] = {Bh, Bl, Bh};

    // ---- ldmatrix per-thread address precompute ----
    const uint32_t kcoA = (lane >> 4) & 1;
    uint32_t aoff[2], asw[2];
    {
        const int roff = (lane & 7) + (((lane >> 3) & 1) << 3);
        #pragma unroll
        for (int mi = 0; mi < 2; ++mi) {
            const int r = wm * 32 + mi * 16 + roff;
            aoff[mi] = (uint32_t)(r * 128);
            asw[mi]  = (uint32_t)(r & 7);
        }
    }
    const uint32_t kcoB = (lane >> 3) & 1;       // TN
    uint32_t boff[4], bsw[4];                    // TN
    uint32_t bco[4], bkoff = 0;                  // NN
    if (!BNN) {
        const int noff = (lane & 7) + (((lane >> 4) & 1) << 3);
        #pragma unroll
        for (int p = 0; p < 4; ++p) {
            const int r = wn * 64 + p * 16 + noff;
            boff[p] = (uint32_t)(r * 128);
            bsw[p]  = (uint32_t)(r & 7);
        }
    } else {
        const int koff = (lane & 7) + (((lane >> 3) & 1) << 3);
        bkoff = (uint32_t)(koff * 256);
        const int ncsel = (lane >> 4) & 1;
        #pragma unroll
        for (int p = 0; p < 4; ++p) {
            const int ncb = wn * 8 + p * 2 + ncsel;
            bco[p] = (uint32_t)((ncb ^ (lane & 7)) << 4);
        }
    }

    float acc[2][8][4];
    #pragma unroll
    for (int mi = 0; mi < 2; ++mi)
        #pragma unroll
        for (int ni = 0; ni < 8; ++ni)
            #pragma unroll
            for (int j = 0; j < 4; ++j) acc[mi][ni][j] = 0.f;

    auto issue = [&](int t) {
        int comp, kc;
        if (NSPLIT == 1) { comp = 0; kc = t; }
        else             { comp = t / NC; kc = t - comp * NC; }
        const int k0 = kc * 64;
        const __half* Ap = Alist[comp];
        const __half* Bp = Blist[comp];
        const uint32_t s = sbase + (uint32_t)(t % STAGES) * STAGE;
        #pragma unroll
        for (int i = 0; i < 4; ++i) {
            cpa16(s + dA[i], Ap + gA[i] + k0);
            if (!BNN) cpa16(s + 16384u + dB[i], Bp + gB[i] + k0);
            else      cpa16(s + 16384u + dB[i], Bp + gB[i] + (size_t)k0 * ldb);
        }
    };

    // prologue: STAGES-1 chunks in flight
    #pragma unroll
    for (int s = 0; s < STAGES - 1; ++s) {
        if (s < T) issue(s);
        asm volatile("cp.async.commit_group;");
    }

    for (int t = 0; t < T; ++t) {
        asm volatile("cp.async.wait_group 1;");  // chunk t resident
        __syncthreads();                          // buf (t-1)%3 free for reuse
        if (t + STAGES - 1 < T) issue(t + STAGES - 1);
        asm volatile("cp.async.commit_group;");

        const uint32_t sA = sbase + (uint32_t)(t % STAGES) * STAGE;
        const uint32_t sB = sA + 16384u;
        #pragma unroll
        for (int kk = 0; kk < 4; ++kk) {
            uint32_t a[2][4];
            #pragma unroll
            for (int mi = 0; mi < 2; ++mi)
                ldsm4(a[mi][0], a[mi][1], a[mi][2], a[mi][3],
                      sA + aoff[mi] + ((((uint32_t)(2 * kk) + kcoA) ^ asw[mi]) << 4));
            uint32_t b[4][4];
            #pragma unroll
            for (int p = 0; p < 4; ++p) {
                if (!BNN)
                    ldsm4(b[p][0], b[p][1], b[p][2], b[p][3],
                          sB + boff[p] + ((((uint32_t)(2 * kk) + kcoB) ^ bsw[p]) << 4));
                else
                    ldsm4t(b[p][0], b[p][1], b[p][2], b[p][3],
                           sB + (uint32_t)kk * 4096u + bkoff + bco[p]);
            }
            #pragma unroll
            for (int mi = 0; mi < 2; ++mi)
                #pragma unroll
                for (int p = 0; p < 4; ++p) {
                    mma16816(acc[mi][2 * p],     a[mi], b[p][0], b[p][1]);
                    mma16816(acc[mi][2 * p + 1], a[mi], b[p][2], b[p][3]);
                }
        }
    }

    // ---- epilogue ----
    const int gid = lane >> 2, qid = lane & 3;
    #pragma unroll
    for (int mi = 0; mi < 2; ++mi) {
        #pragma unroll
        for (int ni = 0; ni < 8; ++ni) {
            const int r = tm0 + wm * 32 + mi * 16 + gid;
            const int c = tn0 + wn * 64 + ni * 8 + qid * 2;
            float v0 = acc[mi][ni][0], v1 = acc[mi][ni][1];
            float v2 = acc[mi][ni][2], v3 = acc[mi][ni][3];
            if (EPI == 1 || EPI == 2) {
                const float2 bb = *reinterpret_cast<const float2*>(bias + c);
                v0 += bb.x; v1 += bb.y; v2 += bb.x; v3 += bb.y;
            }
            if (EPI == 0) {
                *reinterpret_cast<float2*>(Cf + (size_t)r * ldc + c) =
                    make_float2(v0, v1);
                *reinterpret_cast<float2*>(Cf + (size_t)(r + 8) * ldc + c) =
                    make_float2(v2, v3);
            } else if (EPI == 2) {
                *reinterpret_cast<__half2*>(Ch + (size_t)r * ldc + c) =
                    __halves2half2(__float2half_rn(v0), __float2half_rn(v1));
                *reinterpret_cast<__half2*>(Ch + (size_t)(r + 8) * ldc + c) =
                    __halves2half2(__float2half_rn(v2), __float2half_rn(v3));
            } else {
                const __half h0 = __float2half_rn(v0), h1 = __float2half_rn(v1);
                const __half h2 = __float2half_rn(v2), h3 = __float2half_rn(v3);
                const __half l0 = __float2half_rn(v0 - __half2float(h0));
                const __half l1 = __float2half_rn(v1 - __half2float(h1));
                const __half l2 = __float2half_rn(v2 - __half2float(h2));
                const __half l3 = __float2half_rn(v3 - __half2float(h3));
                *reinterpret_cast<__half2*>(Ch + (size_t)r * ldc + c) =
                    __halves2half2(h0, h1);
                *reinterpret_cast<__half2*>(Ch + (size_t)(r + 8) * ldc + c) =
                    __halves2half2(h2, h3);
                *reinterpret_cast<__half2*>(Cl + (size_t)r * ldc + c) =
                    __halves2half2(l0, l1);
                *reinterpret_cast<__half2*>(Cl + (size_t)(r + 8) * ldc + c) =
                    __halves2half2(l2, l3);
            }
        }
    }
}

// ----------------------------------------------------------------------------
// kernels
// ----------------------------------------------------------------------------
__global__ __launch_bounds__(256)
void split_kernel(const float* __restrict__ src, __half* __restrict__ dh,
                  __half* __restrict__ dl, int n4)
{
    const int i = blockIdx.x * blockDim.x + threadIdx.x;
    if (i >= n4) return;
    const float4 v = reinterpret_cast<const float4*>(src)[i];
    const __half h0 = __float2half_rn(v.x), h1 = __float2half_rn(v.y);
    const __half h2 = __float2half_rn(v.z), h3 = __float2half_rn(v.w);
    const __half l0 = __float2half_rn(v.x - __half2float(h0));
    const __half l1 = __float2half_rn(v.y - __half2float(h1));
    const __half l2 = __float2half_rn(v.z - __half2float(h2));
    const __half l3 = __float2half_rn(v.w - __half2float(h3));
    reinterpret_cast<__half2*>(dh)[2 * i]     = __halves2half2(h0, h1);
    reinterpret_cast<__half2*>(dh)[2 * i + 1] = __halves2half2(h2, h3);
    reinterpret_cast<__half2*>(dl)[2 * i]     = __halves2half2(l0, l1);
    reinterpret_cast<__half2*>(dl)[2 * i + 1] = __halves2half2(l2, l3);
}

__global__ __launch_bounds__(256, 2)
void qkv_kernel(const float* __restrict__ bq, const float* __restrict__ bk,
                const float* __restrict__ bv)
{
    const int z = blockIdx.z;
    const __half* Wh = g_wh + (size_t)z * HID * HID;
    const __half* Wl = g_wl + (size_t)z * HID * HID;
    if (z == 0)
        gemm_main<1024, 3, false, 1>(g_xh, g_xl, Wh, Wl, HID, HID,
                                     nullptr, g_qh, g_ql, bq, HID);
    else if (z == 1)
        gemm_main<1024, 3, false, 1>(g_xh, g_xl, Wh, Wl, HID, HID,
                                     nullptr, g_kh, g_kl, bk, HID);
    else
        gemm_main<1024, 3, false, 2>(g_xh, g_xl, Wh, Wl, HID, HID,
                                     nullptr, g_vh, nullptr, bv, HID);
}

__global__ __launch_bounds__(256, 2)
void scores_kernel()
{
    const size_t bo = (size_t)blockIdx.z * SEQ * HID;
    gemm_main<1024, 3, false, 0>(g_qh + bo, g_ql + bo, g_kh + bo, g_kl + bo,
                                 HID, HID,
                                 g_s + (size_t)blockIdx.z * SEQ * SEQ,
                                 nullptr, nullptr, nullptr, SEQ);
}

__global__ __launch_bounds__(256, 2)
void pv_kernel(float* __restrict__ out)
{
    const size_t so = (size_t)blockIdx.z * SEQ * SEQ;
    const size_t vo = (size_t)blockIdx.z * SEQ * HID;
    gemm_main<2048, 1, true, 0>(g_p + so, nullptr, g_vh + vo, nullptr,
                                SEQ, HID, out + vo, nullptr, nullptr,
                                nullptr, HID);
}

__global__ __launch_bounds__(256)
void softmax_kernel()
{
    const float* src = g_s + (size_t)blockIdx.x * SEQ;
    __half* dst = g_p + (size_t)blockIdx.x * SEQ;
    const int t = threadIdx.x;
    __shared__ float red[8];

    const float4* p4 = reinterpret_cast<const float4*>(src);
    float4 u0 = p4[t];
    float4 u1 = p4[t + 256];

    float m = fmaxf(fmaxf(fmaxf(u0.x, u0.y), fmaxf(u0.z, u0.w)),
                    fmaxf(fmaxf(u1.x, u1.y), fmaxf(u1.z, u1.w)));
    #pragma unroll
    for (int off = 16; off; off >>= 1)
        m = fmaxf(m, __shfl_xor_sync(0xffffffffu, m, off));
    if ((t & 31) == 0) red[t >> 5] = m;
    __syncthreads();
    if (t < 8) {
        float mm = red[t];
        #pragma unroll
        for (int off = 4; off; off >>= 1)
            mm = fmaxf(mm, __shfl_xor_sync(0xffu, mm, off));
        if (t == 0) red[0] = mm;
    }
    __syncthreads();
    m = red[0];
    __syncthreads();

    u0.x = expf(u0.x - m); u0.y = expf(u0.y - m);
    u0.z = expf(u0.z - m); u0.w = expf(u0.w - m);
    u1.x = expf(u1.x - m); u1.y = expf(u1.y - m);
    u1.z = expf(u1.z - m); u1.w = expf(u1.w - m);

    float s = (u0.x + u0.y + u0.z + u0.w) + (u1.x + u1.y + u1.z + u1.w);
    #pragma unroll
    for (int off = 16; off; off >>= 1)
        s += __shfl_xor_sync(0xffffffffu, s, off);
    if ((t & 31) == 0) red[t >> 5] = s;
    __syncthreads();
    if (t < 8) {
        float ss = red[t];
        #pragma unroll
        for (int off = 4; off; off >>= 1)
            ss += __shfl_xor_sync(0xffu, ss, off);
        if (t == 0) red[0] = ss;
    }
    __syncthreads();
    const float inv = 1.0f / red[0];

    __half2* d2 = reinterpret_cast<__half2*>(dst);
    d2[2 * t]           = __halves2half2(__float2half_rn(u0.x * inv),
                                         __float2half_rn(u0.y * inv));
    d2[2 * t + 1]       = __halves2half2(__float2half_rn(u0.z * inv),
                                         __float2half_rn(u0.w * inv));
    d2[512 + 2 * t]     = __halves2half2(__float2half_rn(u1.x * inv),
                                         __float2half_rn(u1.y * inv));
    d2[512 + 2 * t + 1] = __halves2half2(__float2half_rn(u1.z * inv),
                                         __float2half_rn(u1.w * inv));
}

// ----------------------------------------------------------------------------
// launch
// ----------------------------------------------------------------------------
#define GEMM_SMEM 98304

extern "C" void kernel_launch(void* const* d_in, const int* in_sizes, int n_in,
                              void* d_out, int out_size)
{
    (void)in_sizes; (void)n_in; (void)out_size;
    const float* x  = (const float*)d_in[0];
    const float* Wq = (const float*)d_in[1];
    const float* bq = (const float*)d_in[2];
    const float* Wk = (const float*)d_in[3];
    const float* bk = (const float*)d_in[4];
    const float* Wv = (const float*)d_in[5];
    const float* bv = (const float*)d_in[6];
    float* out = (float*)d_out;

    cudaFuncSetAttribute(qkv_kernel,
        cudaFuncAttributeMaxDynamicSharedMemorySize, GEMM_SMEM);
    cudaFuncSetAttribute(scores_kernel,
        cudaFuncAttributeMaxDynamicSharedMemorySize, GEMM_SMEM);
    cudaFuncSetAttribute(pv_kernel,
        cudaFuncAttributeMaxDynamicSharedMemorySize, GEMM_SMEM);

    __half *xh, *xl, *wh, *wl;
    cudaGetSymbolAddress((void**)&xh, g_xh);
    cudaGetSymbolAddress((void**)&xl, g_xl);
    cudaGetSymbolAddress((void**)&wh, g_wh);
    cudaGetSymbolAddress((void**)&wl, g_wl);

    // 0) hi/lo splits of x and the three weight matrices
    split_kernel<<<(MTOT * HID / 4 + 255) / 256, 256>>>(x, xh, xl, MTOT * HID / 4);
    split_kernel<<<(HID * HID / 4 + 255) / 256, 256>>>(Wq, wh, wl, HID * HID / 4);
    split_kernel<<<(HID * HID / 4 + 255) / 256, 256>>>(
        Wk, wh + (size_t)HID * HID, wl + (size_t)HID * HID, HID * HID / 4);
    split_kernel<<<(HID * HID / 4 + 255) / 256, 256>>>(
        Wv, wh + (size_t)2 * HID * HID, wl + (size_t)2 * HID * HID, HID * HID / 4);

    // 1) q/k/v projections (3x-fp16 split; q,k stored pre-split, v as fp16)
    qkv_kernel<<<dim3(HID / 128, MTOT / 128, 3), 256, GEMM_SMEM>>>(bq, bk, bv);
    // 2) scores = q k^T (3x-fp16 split) -> fp32
    scores_kernel<<<dim3(SEQ / 128, SEQ / 128, BATCH), 256, GEMM_SMEM>>>();
    // 3) softmax rows -> fp16 P
    softmax_kernel<<<BATCH * SEQ, 256>>>();
    // 4) out = P v (1x fp16)
    pv_kernel<<<dim3(HID / 128, SEQ / 128, BATCH), 256, GEMM_SMEM>>>(out);
}

// round 5
// speedup vs baseline: 3.0521x; 1.1243x over previous
#include <cuda_runtime.h>
#include <cuda_fp16.h>
#include <cstdint>

// ============================================================================
// SelfAttention: out = softmax( (xWq^T+bq)(xWk^T+bk)^T ) (xWv^T+bv)
// B=4, S=2048, H=1024 (fp32 in/out)
// All GEMMs: legacy mma.sync m16n8k16 fp16 (tcgen05 unavailable: target sm_100)
// Precision: 3x-FP16 hi/lo split for QKV(q,k) + scores; 1x-FP16 for V and PV.
// Softmax: threshold-gated exp (elements < rowmax-17 contribute <4e-8 -> skip).
// ============================================================================

#define BATCH 4
#define SEQ   2048
#define HID   1024
#define MTOT  (BATCH*SEQ)          // 8192

// ---- scratch (device globals; allocation-free per harness rules) ----
__device__ __half g_xh[(size_t)MTOT * HID];
__device__ __half g_xl[(size_t)MTOT * HID];
__device__ __half g_wh[(size_t)3 * HID * HID];
__device__ __half g_wl[(size_t)3 * HID * HID];
__device__ __half g_qh[(size_t)MTOT * HID];
__device__ __half g_ql[(size_t)MTOT * HID];
__device__ __half g_kh[(size_t)MTOT * HID];
__device__ __half g_kl[(size_t)MTOT * HID];
__device__ __half g_vh[(size_t)MTOT * HID];
__device__ float  g_s [(size_t)BATCH * SEQ * SEQ];
__device__ __half g_p [(size_t)BATCH * SEQ * SEQ];

// ----------------------------------------------------------------------------
// helpers
// ----------------------------------------------------------------------------
__device__ __forceinline__ uint32_t smem_u32(const void* p) {
    uint32_t a;
    asm("{ .reg .u64 t; cvta.to.shared.u64 t, %1; cvt.u32.u64 %0, t; }"
        : "=r"(a) : "l"(p));
    return a;
}

__device__ __forceinline__ void cpa16(uint32_t dst, const void* src) {
    asm volatile("cp.async.cg.shared.global [%0], [%1], 16;"
                 :: "r"(dst), "l"(src));
}

__device__ __forceinline__ void ldsm4(uint32_t& r0, uint32_t& r1,
                                      uint32_t& r2, uint32_t& r3, uint32_t a) {
    asm volatile("ldmatrix.sync.aligned.m8n8.x4.shared.b16 {%0,%1,%2,%3}, [%4];"
                 : "=r"(r0), "=r"(r1), "=r"(r2), "=r"(r3) : "r"(a));
}
__device__ __forceinline__ void ldsm4t(uint32_t& r0, uint32_t& r1,
                                       uint32_t& r2, uint32_t& r3, uint32_t a) {
    asm volatile("ldmatrix.sync.aligned.m8n8.x4.trans.shared.b16 {%0,%1,%2,%3}, [%4];"
                 : "=r"(r0), "=r"(r1), "=r"(r2), "=r"(r3) : "r"(a));
}

__device__ __forceinline__ void mma16816(float c[4], const uint32_t a[4],
                                         uint32_t b0, uint32_t b1) {
    asm volatile(
        "mma.sync.aligned.m16n8k16.row.col.f32.f16.f16.f32 "
        "{%0,%1,%2,%3}, {%4,%5,%6,%7}, {%8,%9}, {%0,%1,%2,%3};\n"
        : "+f"(c[0]), "+f"(c[1]), "+f"(c[2]), "+f"(c[3])
        : "r"(a[0]), "r"(a[1]), "r"(a[2]), "r"(a[3]), "r"(b0), "r"(b1));
}

// ============================================================================
// GEMM core: 128x128 CTA tile, BK=64 halves, 3-stage cp.async pipeline.
//   BNN=false: TN — A[M,K], B[N,K] both K-major (C = A * B^T)
//   BNN=true : NN — A[M,K] K-major, B[K,N] N-major (C = A * B)
//   NSPLIT=3 : products Ah*Bh + Ah*Bl + Al*Bh ; NSPLIT=1 : Ah*Bh
//   EPI: 0 = fp32 store; 1 = bias + hi/lo half split store; 2 = bias + half
// ============================================================================
template<int KVAL, int NSPLIT, bool BNN, int EPI>
__device__ __forceinline__ void gemm_main(
    const __half* __restrict__ Ah, const __half* __restrict__ Al,
    const __half* __restrict__ Bh, const __half* __restrict__ Bl,
    int lda, int ldb,
    float* __restrict__ Cf, __half* __restrict__ Ch, __half* __restrict__ Cl,
    const float* __restrict__ bias, int ldc)
{
    constexpr int NC = KVAL / 64;
    constexpr int T  = NSPLIT * NC;
    constexpr int STAGES = 3;
    constexpr uint32_t STAGE = 32768u;

    extern __shared__ __align__(16) char smem[];
    const uint32_t sbase = smem_u32(smem);

    const int tid  = threadIdx.x;
    const int lane = tid & 31;
    const int warp = tid >> 5;
    const int wm = warp & 3;
    const int wn = warp >> 2;
    const int tm0 = blockIdx.y * 128;
    const int tn0 = blockIdx.x * 128;

    uint32_t dA[4], gA[4], dB[4], gB[4];
    #pragma unroll
    for (int i = 0; i < 4; ++i) {
        const int slot = tid + i * 256;
        { const int r = slot >> 3, c = slot & 7;
          dA[i] = (uint32_t)(r * 128 + ((c ^ (r & 7)) << 4));
          gA[i] = (uint32_t)((tm0 + r) * lda + c * 8); }
        if (!BNN) {
            const int r = slot >> 3, c = slot & 7;
            dB[i] = (uint32_t)(r * 128 + ((c ^ (r & 7)) << 4));
            gB[i] = (uint32_t)((tn0 + r) * ldb + c * 8);
        } else {
            const int r = slot >> 4, c = slot & 15;
            dB[i] = (uint32_t)(r * 256 + ((c ^ (r & 7)) << 4));
            gB[i] = (uint32_t)(r * ldb + tn0 + c * 8);
        }
    }

    const __half* const Alist[3] = {Ah, Ah, Al};
    const __half* const Blist[3] = {Bh, Bl, Bh};

    const uint32_t kcoA = (lane >> 4) & 1;
    uint32_t aoff[2], asw[2];
    {
        const int roff = (lane & 7) + (((lane >> 3) & 1) << 3);
        #pragma unroll
        for (int mi = 0; mi < 2; ++mi) {
            const int r = wm * 32 + mi * 16 + roff;
            aoff[mi] = (uint32_t)(r * 128);
            asw[mi]  = (uint32_t)(r & 7);
        }
    }
    const uint32_t kcoB = (lane >> 3) & 1;
    uint32_t boff[4], bsw[4];
    uint32_t bco[4], bkoff = 0;
    if (!BNN) {
        const int noff = (lane & 7) + (((lane >> 4) & 1) << 3);
        #pragma unroll
        for (int p = 0; p < 4; ++p) {
            const int r = wn * 64 + p * 16 + noff;
            boff[p] = (uint32_t)(r * 128);
            bsw[p]  = (uint32_t)(r & 7);
        }
    } else {
        const int koff = (lane & 7) + (((lane >> 3) & 1) << 3);
        bkoff = (uint32_t)(koff * 256);
        const int ncsel = (lane >> 4) & 1;
        #pragma unroll
        for (int p = 0; p < 4; ++p) {
            const int ncb = wn * 8 + p * 2 + ncsel;
            bco[p] = (uint32_t)((ncb ^ (lane & 7)) << 4);
        }
    }

    float acc[2][8][4];
    #pragma unroll
    for (int mi = 0; mi < 2; ++mi)
        #pragma unroll
        for (int ni = 0; ni < 8; ++ni)
            #pragma unroll
            for (int j = 0; j < 4; ++j) acc[mi][ni][j] = 0.f;

    auto issue = [&](int t) {
        int comp, kc;
        if (NSPLIT == 1) { comp = 0; kc = t; }
        else             { comp = t / NC; kc = t - comp * NC; }
        const int k0 = kc * 64;
        const __half* Ap = Alist[comp];
        const __half* Bp = Blist[comp];
        const uint32_t s = sbase + (uint32_t)(t % STAGES) * STAGE;
        #pragma unroll
        for (int i = 0; i < 4; ++i) {
            cpa16(s + dA[i], Ap + gA[i] + k0);
            if (!BNN) cpa16(s + 16384u + dB[i], Bp + gB[i] + k0);
            else      cpa16(s + 16384u + dB[i], Bp + gB[i] + (size_t)k0 * ldb);
        }
    };

    #pragma unroll
    for (int s = 0; s < STAGES - 1; ++s) {
        if (s < T) issue(s);
        asm volatile("cp.async.commit_group;");
    }

    for (int t = 0; t < T; ++t) {
        asm volatile("cp.async.wait_group 1;");
        __syncthreads();
        if (t + STAGES - 1 < T) issue(t + STAGES - 1);
        asm volatile("cp.async.commit_group;");

        const uint32_t sA = sbase + (uint32_t)(t % STAGES) * STAGE;
        const uint32_t sB = sA + 16384u;
        #pragma unroll
        for (int kk = 0; kk < 4; ++kk) {
            uint32_t a[2][4];
            #pragma unroll
            for (int mi = 0; mi < 2; ++mi)
                ldsm4(a[mi][0], a[mi][1], a[mi][2], a[mi][3],
                      sA + aoff[mi] + ((((uint32_t)(2 * kk) + kcoA) ^ asw[mi]) << 4));
            uint32_t b[4][4];
            #pragma unroll
            for (int p = 0; p < 4; ++p) {
                if (!BNN)
                    ldsm4(b[p][0], b[p][1], b[p][2], b[p][3],
                          sB + boff[p] + ((((uint32_t)(2 * kk) + kcoB) ^ bsw[p]) << 4));
                else
                    ldsm4t(b[p][0], b[p][1], b[p][2], b[p][3],
                           sB + (uint32_t)kk * 4096u + bkoff + bco[p]);
            }
            #pragma unroll
            for (int mi = 0; mi < 2; ++mi)
                #pragma unroll
                for (int p = 0; p < 4; ++p) {
                    mma16816(acc[mi][2 * p],     a[mi], b[p][0], b[p][1]);
                    mma16816(acc[mi][2 * p + 1], a[mi], b[p][2], b[p][3]);
                }
        }
    }

    // ---- epilogue ----
    const int gid = lane >> 2, qid = lane & 3;
    #pragma unroll
    for (int mi = 0; mi < 2; ++mi) {
        #pragma unroll
        for (int ni = 0; ni < 8; ++ni) {
            const int r = tm0 + wm * 32 + mi * 16 + gid;
            const int c = tn0 + wn * 64 + ni * 8 + qid * 2;
            float v0 = acc[mi][ni][0], v1 = acc[mi][ni][1];
            float v2 = acc[mi][ni][2], v3 = acc[mi][ni][3];
            if (EPI == 1 || EPI == 2) {
                const float2 bb = *reinterpret_cast<const float2*>(bias + c);
                v0 += bb.x; v1 += bb.y; v2 += bb.x; v3 += bb.y;
            }
            if (EPI == 0) {
                *reinterpret_cast<float2*>(Cf + (size_t)r * ldc + c) =
                    make_float2(v0, v1);
                *reinterpret_cast<float2*>(Cf + (size_t)(r + 8) * ldc + c) =
                    make_float2(v2, v3);
            } else if (EPI == 2) {
                *reinterpret_cast<__half2*>(Ch + (size_t)r * ldc + c) =
                    __halves2half2(__float2half_rn(v0), __float2half_rn(v1));
                *reinterpret_cast<__half2*>(Ch + (size_t)(r + 8) * ldc + c) =
                    __halves2half2(__float2half_rn(v2), __float2half_rn(v3));
            } else {
                const __half h0 = __float2half_rn(v0), h1 = __float2half_rn(v1);
                const __half h2 = __float2half_rn(v2), h3 = __float2half_rn(v3);
                const __half l0 = __float2half_rn(v0 - __half2float(h0));
                const __half l1 = __float2half_rn(v1 - __half2float(h1));
                const __half l2 = __float2half_rn(v2 - __half2float(h2));
                const __half l3 = __float2half_rn(v3 - __half2float(h3));
                *reinterpret_cast<__half2*>(Ch + (size_t)r * ldc + c) =
                    __halves2half2(h0, h1);
                *reinterpret_cast<__half2*>(Ch + (size_t)(r + 8) * ldc + c) =
                    __halves2half2(h2, h3);
                *reinterpret_cast<__half2*>(Cl + (size_t)r * ldc + c) =
                    __halves2half2(l0, l1);
                *reinterpret_cast<__half2*>(Cl + (size_t)(r + 8) * ldc + c) =
                    __halves2half2(l2, l3);
            }
        }
    }
}

// ----------------------------------------------------------------------------
// split kernels
// ----------------------------------------------------------------------------
__device__ __forceinline__ void split4(const float4 v, __half2* dh, __half2* dl) {
    const __half h0 = __float2half_rn(v.x), h1 = __float2half_rn(v.y);
    const __half h2 = __float2half_rn(v.z), h3 = __float2half_rn(v.w);
    dh[0] = __halves2half2(h0, h1);
    dh[1] = __halves2half2(h2, h3);
    dl[0] = __halves2half2(__float2half_rn(v.x - __half2float(h0)),
                           __float2half_rn(v.y - __half2float(h1)));
    dl[1] = __halves2half2(__float2half_rn(v.z - __half2float(h2)),
                           __float2half_rn(v.w - __half2float(h3)));
}

__global__ __launch_bounds__(256)
void split_x_kernel(const float* __restrict__ src)
{
    const int i = blockIdx.x * blockDim.x + threadIdx.x;
    const float4 v = reinterpret_cast<const float4*>(src)[i];
    split4(v, reinterpret_cast<__half2*>(g_xh) + 2 * i,
              reinterpret_cast<__half2*>(g_xl) + 2 * i);
}

__global__ __launch_bounds__(256)
void split_w_kernel(const float* __restrict__ Wq, const float* __restrict__ Wk,
                    const float* __restrict__ Wv)
{
    const float* src = (blockIdx.z == 0) ? Wq : (blockIdx.z == 1) ? Wk : Wv;
    const size_t off = (size_t)blockIdx.z * (HID * HID / 4);
    const int i = blockIdx.x * blockDim.x + threadIdx.x;
    const float4 v = reinterpret_cast<const float4*>(src)[i];
    split4(v, reinterpret_cast<__half2*>(g_wh) + 2 * (off + i),
              reinterpret_cast<__half2*>(g_wl) + 2 * (off + i));
}

// ----------------------------------------------------------------------------
// GEMM kernels
// ----------------------------------------------------------------------------
__global__ __launch_bounds__(256, 2)
void qkv_kernel(const float* __restrict__ bq, const float* __restrict__ bk,
                const float* __restrict__ bv)
{
    const int z = blockIdx.z;
    const __half* Wh = g_wh + (size_t)z * HID * HID;
    const __half* Wl = g_wl + (size_t)z * HID * HID;
    if (z == 0)
        gemm_main<1024, 3, false, 1>(g_xh, g_xl, Wh, Wl, HID, HID,
                                     nullptr, g_qh, g_ql, bq, HID);
    else if (z == 1)
        gemm_main<1024, 3, false, 1>(g_xh, g_xl, Wh, Wl, HID, HID,
                                     nullptr, g_kh, g_kl, bk, HID);
    else  // V: single-product fp16 is enough (error ~2e-4, enters output directly)
        gemm_main<1024, 1, false, 2>(g_xh, nullptr, Wh, nullptr, HID, HID,
                                     nullptr, g_vh, nullptr, bv, HID);
}

__global__ __launch_bounds__(256, 2)
void scores_kernel()
{
    const size_t bo = (size_t)blockIdx.z * SEQ * HID;
    gemm_main<1024, 3, false, 0>(g_qh + bo, g_ql + bo, g_kh + bo, g_kl + bo,
                                 HID, HID,
                                 g_s + (size_t)blockIdx.z * SEQ * SEQ,
                                 nullptr, nullptr, nullptr, SEQ);
}

__global__ __launch_bounds__(256, 2)
void pv_kernel(float* __restrict__ out)
{
    const size_t so = (size_t)blockIdx.z * SEQ * SEQ;
    const size_t vo = (size_t)blockIdx.z * SEQ * HID;
    gemm_main<2048, 1, true, 0>(g_p + so, nullptr, g_vh + vo, nullptr,
                                SEQ, HID, out + vo, nullptr, nullptr,
                                nullptr, HID);
}

// ----------------------------------------------------------------------------
// softmax with threshold-gated exp
//   Elements below rowmax-17 contribute < 4.2e-8 each (worst-case total
//   2048*e^-17 = 8.4e-5 relative) -> treated as zero, skipping MUFU for
//   ~99.6% of warp-groups.
// ----------------------------------------------------------------------------
__global__ __launch_bounds__(256)
void softmax_kernel()
{
    const float* src = g_s + (size_t)blockIdx.x * SEQ;
    __half* dst = g_p + (size_t)blockIdx.x * SEQ;
    const int t = threadIdx.x;
    __shared__ float red[8];

    const float4* p4 = reinterpret_cast<const float4*>(src);
    float4 u0 = p4[t];
    float4 u1 = p4[t + 256];

    const float m0 = fmaxf(fmaxf(u0.x, u0.y), fmaxf(u0.z, u0.w));
    const float m1 = fmaxf(fmaxf(u1.x, u1.y), fmaxf(u1.z, u1.w));
    float m = fmaxf(m0, m1);
    #pragma unroll
    for (int off = 16; off; off >>= 1)
        m = fmaxf(m, __shfl_xor_sync(0xffffffffu, m, off));
    if ((t & 31) == 0) red[t >> 5] = m;
    __syncthreads();
    if (t < 8) {
        float mm = red[t];
        #pragma unroll
        for (int off = 4; off; off >>= 1)
            mm = fmaxf(mm, __shfl_xor_sync(0xffu, mm, off));
        if (t == 0) red[0] = mm;
    }
    __syncthreads();
    m = red[0];
    __syncthreads();

    const float thr = m - 17.0f;

    if (__any_sync(0xffffffffu, m0 > thr)) {
        u0.x = (u0.x > thr) ? __expf(u0.x - m) : 0.f;
        u0.y = (u0.y > thr) ? __expf(u0.y - m) : 0.f;
        u0.z = (u0.z > thr) ? __expf(u0.z - m) : 0.f;
        u0.w = (u0.w > thr) ? __expf(u0.w - m) : 0.f;
    } else {
        u0.x = u0.y = u0.z = u0.w = 0.f;
    }
    if (__any_sync(0xffffffffu, m1 > thr)) {
        u1.x = (u1.x > thr) ? __expf(u1.x - m) : 0.f;
        u1.y = (u1.y > thr) ? __expf(u1.y - m) : 0.f;
        u1.z = (u1.z > thr) ? __expf(u1.z - m) : 0.f;
        u1.w = (u1.w > thr) ? __expf(u1.w - m) : 0.f;
    } else {
        u1.x = u1.y = u1.z = u1.w = 0.f;
    }

    float s = (u0.x + u0.y + u0.z + u0.w) + (u1.x + u1.y + u1.z + u1.w);
    #pragma unroll
    for (int off = 16; off; off >>= 1)
        s += __shfl_xor_sync(0xffffffffu, s, off);
    if ((t & 31) == 0) red[t >> 5] = s;
    __syncthreads();
    if (t < 8) {
        float ss = red[t];
        #pragma unroll
        for (int off = 4; off; off >>= 1)
            ss += __shfl_xor_sync(0xffu, ss, off);
        if (t == 0) red[0] = ss;
    }
    __syncthreads();
    const float inv = 1.0f / red[0];

    __half2* d2 = reinterpret_cast<__half2*>(dst);
    d2[2 * t]           = __halves2half2(__float2half_rn(u0.x * inv),
                                         __float2half_rn(u0.y * inv));
    d2[2 * t + 1]       = __halves2half2(__float2half_rn(u0.z * inv),
                                         __float2half_rn(u0.w * inv));
    d2[512 + 2 * t]     = __halves2half2(__float2half_rn(u1.x * inv),
                                         __float2half_rn(u1.y * inv));
    d2[512 + 2 * t + 1] = __halves2half2(__float2half_rn(u1.z * inv),
                                         __float2half_rn(u1.w * inv));
}

// ----------------------------------------------------------------------------
// launch
// ----------------------------------------------------------------------------
#define GEMM_SMEM 98304

extern "C" void kernel_launch(void* const* d_in, const int* in_sizes, int n_in,
                              void* d_out, int out_size)
{
    (void)in_sizes; (void)n_in; (void)out_size;
    const float* x  = (const float*)d_in[0];
    const float* Wq = (const float*)d_in[1];
    const float* bq = (const float*)d_in[2];
    const float* Wk = (const float*)d_in[3];
    const float* bk = (const float*)d_in[4];
    const float* Wv = (const float*)d_in[5];
    const float* bv = (const float*)d_in[6];
    float* out = (float*)d_out;

    cudaFuncSetAttribute(qkv_kernel,
        cudaFuncAttributeMaxDynamicSharedMemorySize, GEMM_SMEM);
    cudaFuncSetAttribute(scores_kernel,
        cudaFuncAttributeMaxDynamicSharedMemorySize, GEMM_SMEM);
    cudaFuncSetAttribute(pv_kernel,
        cudaFuncAttributeMaxDynamicSharedMemorySize, GEMM_SMEM);

    // 0) hi/lo splits of x and the three weight matrices
    split_x_kernel<<<MTOT * HID / 4 / 256, 256>>>(x);
    split_w_kernel<<<dim3(HID * HID / 4 / 256, 1, 3), 256>>>(Wq, Wk, Wv);

    // 1) q/k/v projections (q,k: 3x split; v: 1x fp16)
    qkv_kernel<<<dim3(HID / 128, MTOT / 128, 3), 256, GEMM_SMEM>>>(bq, bk, bv);
    // 2) scores = q k^T (3x split) -> fp32
    scores_kernel<<<dim3(SEQ / 128, SEQ / 128, BATCH), 256, GEMM_SMEM>>>();
    // 3) softmax rows -> fp16 P (threshold-gated exp)
    softmax_kernel<<<BATCH * SEQ, 256>>>();
    // 4) out = P v (1x fp16)
    pv_kernel<<<dim3(HID / 128, SEQ / 128, BATCH), 256, GEMM_SMEM>>>(out);
}